// round 1
// baseline (speedup 1.0000x reference)
#include <cuda_runtime.h>

// Shapes fixed by the problem: B=4, T=2048, D=768 -> E=2*D=1536, H=256.
#define B_DIM 4
#define T_DIM 2048
#define E_DIM 1536
#define H_DIM 256

// Scratch (allocation-free rule: __device__ globals).
__device__ float g_colsum[B_DIM * E_DIM];   // sum over T of x, per (b, flat-feature)
__device__ float g_hidden[B_DIM * H_DIM];   // pre-activation hidden accumulator

// ---------------------------------------------------------------------------
// Kernel 0: zero the accumulators (d_out scratch is poisoned; we own these).
// ---------------------------------------------------------------------------
__global__ void zero_kernel() {
    int i = blockIdx.x * blockDim.x + threadIdx.x;
    if (i < B_DIM * E_DIM) g_colsum[i] = 0.0f;
    if (i < B_DIM * H_DIM) g_hidden[i] = 0.0f;
}

// ---------------------------------------------------------------------------
// Kernel 1: column sums over T.  x is (B, T, E) fp32 row-major in memory
// (the (D,2) trailing dims flatten to E=1536 contiguously, matching the
// reference's reshape).  Each block: 128 threads x float4 = 512 columns,
// one T-chunk of 64 rows.  Grid: (12 col-chunks, 32 t-chunks) = 384 blocks.
// Fully coalesced: 128 consecutive float4 per row per block.
// ---------------------------------------------------------------------------
#define NT_CHUNKS 32
#define T_CHUNK   (T_DIM / NT_CHUNKS)   // 64
#define COLS4     (E_DIM / 4)           // 384 float4 per row
#define CC_PER_B  3                     // 384 / 128

__global__ void colsum_kernel(const float* __restrict__ x) {
    int cb  = blockIdx.x;               // 0..11
    int b   = cb / CC_PER_B;
    int cc  = cb % CC_PER_B;
    int c4  = cc * 128 + threadIdx.x;   // float4 column index in [0, 384)
    int t0  = blockIdx.y * T_CHUNK;

    const float4* xp = reinterpret_cast<const float4*>(x)
                     + (size_t)(b * T_DIM + t0) * COLS4 + c4;

    float4 acc = make_float4(0.f, 0.f, 0.f, 0.f);
#pragma unroll 8
    for (int t = 0; t < T_CHUNK; t++) {
        float4 v = xp[(size_t)t * COLS4];
        acc.x += v.x; acc.y += v.y; acc.z += v.z; acc.w += v.w;
    }

    float* dst = &g_colsum[b * E_DIM + c4 * 4];
    atomicAdd(dst + 0, acc.x);
    atomicAdd(dst + 1, acc.y);
    atomicAdd(dst + 2, acc.z);
    atomicAdd(dst + 3, acc.w);
}

// ---------------------------------------------------------------------------
// Kernel 2: hidden[b][j] += sum_{d in chunk} mean[b][d] * W1[d][j].
// 16 blocks x 96 rows of W1 each; W1 rows are 256 floats -> coalesced.
// Means broadcast from shared memory.  ReLU deferred to the epilogue
// (must happen after full accumulation).
// ---------------------------------------------------------------------------
#define D_CHUNK 96                      // 16 * 96 = 1536

__global__ void gemv1_kernel(const float* __restrict__ W1) {
    __shared__ float s[B_DIM][D_CHUNK];
    int d0 = blockIdx.x * D_CHUNK;

    for (int i = threadIdx.x; i < B_DIM * D_CHUNK; i += blockDim.x) {
        int b = i / D_CHUNK, dd = i % D_CHUNK;
        s[b][dd] = g_colsum[b * E_DIM + d0 + dd] * (1.0f / (float)T_DIM);
    }
    __syncthreads();

    int j = threadIdx.x;                // 256 threads = H_DIM
    float a0 = 0.f, a1 = 0.f, a2 = 0.f, a3 = 0.f;
#pragma unroll 4
    for (int dd = 0; dd < D_CHUNK; dd++) {
        float w = W1[(size_t)(d0 + dd) * H_DIM + j];
        a0 = fmaf(s[0][dd], w, a0);
        a1 = fmaf(s[1][dd], w, a1);
        a2 = fmaf(s[2][dd], w, a2);
        a3 = fmaf(s[3][dd], w, a3);
    }
    atomicAdd(&g_hidden[0 * H_DIM + j], a0);
    atomicAdd(&g_hidden[1 * H_DIM + j], a1);
    atomicAdd(&g_hidden[2 * H_DIM + j], a2);
    atomicAdd(&g_hidden[3 * H_DIM + j], a3);
}

// ---------------------------------------------------------------------------
// Kernel 3: surprise[b] = sum_j relu(hidden[b][j] + b1[j]) * W2[j] + b2.
// Then zero-fill the remaining output slots: best_action_idx == 0 ALWAYS
// (all 32 replicated actions are bit-identical -> argmax of equal values
// is index 0; int 0 and float 0.0 share the all-zero bit pattern).
// ---------------------------------------------------------------------------
__global__ void final_kernel(const float* __restrict__ b1,
                             const float* __restrict__ W2,
                             const float* __restrict__ b2,
                             float* __restrict__ out, int out_size) {
    __shared__ float red[B_DIM][8];     // 8 warps
    int j    = threadIdx.x;             // 256 threads
    int lane = j & 31, warp = j >> 5;

    float w2 = W2[j];
    float bb = b1[j];
    float v[B_DIM];
#pragma unroll
    for (int b = 0; b < B_DIM; b++) {
        float h = g_hidden[b * H_DIM + j] + bb;
        v[b] = fmaxf(h, 0.0f) * w2;
    }
#pragma unroll
    for (int off = 16; off > 0; off >>= 1)
#pragma unroll
        for (int b = 0; b < B_DIM; b++)
            v[b] += __shfl_down_sync(0xffffffffu, v[b], off);

    if (lane == 0)
#pragma unroll
        for (int b = 0; b < B_DIM; b++) red[b][warp] = v[b];
    __syncthreads();

    if (j < B_DIM && j < out_size) {
        float s = 0.f;
#pragma unroll
        for (int w = 0; w < 8; w++) s += red[j][w];
        out[j] = s + b2[0];
    }
    // Zero-fill remaining slots (the argmax output slot -> 0).
    for (int i = B_DIM + threadIdx.x; i < out_size; i += blockDim.x)
        out[i] = 0.0f;
}

// ---------------------------------------------------------------------------
// Launch: inputs per metadata order: x, W1, b1, W2, b2, Wd, bd, Wu, bu.
// Wd/bd/Wu/bu are provably dead (argmax of identical values == 0).
// ---------------------------------------------------------------------------
extern "C" void kernel_launch(void* const* d_in, const int* in_sizes, int n_in,
                              void* d_out, int out_size) {
    const float* x  = (const float*)d_in[0];
    const float* W1 = (const float*)d_in[1];
    const float* b1 = (const float*)d_in[2];
    const float* W2 = (const float*)d_in[3];
    const float* b2 = (const float*)d_in[4];
    float* out = (float*)d_out;

    zero_kernel<<<(B_DIM * E_DIM + 255) / 256, 256>>>();

    dim3 grid1(B_DIM * CC_PER_B, NT_CHUNKS);   // (12, 32)
    colsum_kernel<<<grid1, 128>>>(x);

    gemv1_kernel<<<E_DIM / D_CHUNK, H_DIM>>>(W1);   // 16 blocks, 256 thr

    final_kernel<<<1, H_DIM>>>(b1, W2, b2, out, out_size);
}

// round 2
// speedup vs baseline: 1.2600x; 1.2600x over previous
#include <cuda_runtime.h>

// Shapes fixed by the problem: B=4, T=2048, D=768 -> E=2*D=1536, H=256.
#define B_DIM 4
#define T_DIM 2048
#define E_DIM 1536
#define H_DIM 256

#define NT_CHUNKS 32
#define T_CHUNK   (T_DIM / NT_CHUNKS)      // 64
#define COLS4     (E_DIM / 4)              // 384 float4 per (b,t) row
#define CB_CHUNKS 6                        // 6 * 256 = 1536 = B*COLS4
#define N_BLOCKS  (CB_CHUNKS * NT_CHUNKS)  // 192
#define N_TAIL    16
#define D_CHUNK   (E_DIM / N_TAIL)         // 96

// Scratch: __device__ globals (allocation-free rule).
// Invariant: zero at kernel entry. Statics start zero; block 0 re-zeroes at
// the end of every call, so each graph replay sees clean state.
__device__ float    g_colsum[B_DIM * E_DIM];
__device__ float    g_hpart[N_TAIL][B_DIM][H_DIM];
__device__ unsigned g_c1;
__device__ unsigned g_c2;

__global__ void __launch_bounds__(256, 2)
curiosity_fused(const float* __restrict__ x,
                const float* __restrict__ W1,
                const float* __restrict__ b1,
                const float* __restrict__ W2,
                const float* __restrict__ b2,
                float* __restrict__ out, int out_size) {
    const int tid = threadIdx.x;
    const int bid = blockIdx.x;

    // ---------------- Phase 1: column sum over T (all 192 blocks) ----------
    {
        int cb = bid % CB_CHUNKS;          // which 256-wide float4 col chunk
        int tb = bid / CB_CHUNKS;          // which T chunk
        int gc = cb * 256 + tid;           // global (b, c4) in [0, 1536)
        int b  = gc / COLS4;
        int c4 = gc % COLS4;
        int t0 = tb * T_CHUNK;

        const float4* xp = reinterpret_cast<const float4*>(x)
                         + (size_t)(b * T_DIM + t0) * COLS4 + c4;

        float4 acc = make_float4(0.f, 0.f, 0.f, 0.f);
#pragma unroll 8
        for (int t = 0; t < T_CHUNK; t++) {
            float4 v = xp[(size_t)t * COLS4];
            acc.x += v.x; acc.y += v.y; acc.z += v.z; acc.w += v.w;
        }
        float* dst = &g_colsum[gc * 4];
        atomicAdd(dst + 0, acc.x);
        atomicAdd(dst + 1, acc.y);
        atomicAdd(dst + 2, acc.z);
        atomicAdd(dst + 3, acc.w);

        __syncthreads();                   // all block atomics issued
        if (tid == 0) {
            __threadfence();               // release colsum before counter
            atomicAdd(&g_c1, 1u);
        }
    }

    // ---------------- Phase 2: GEMV1 tail (blocks 0..15) -------------------
    __shared__ float s[B_DIM][D_CHUNK];
    if (bid < N_TAIL) {
        const int j  = tid;                // hidden index, 256 threads = H
        const int d0 = bid * D_CHUNK;

        // Preload this block's W1 chunk into registers BEFORE spinning so the
        // loads overlap with the remaining colsum DRAM traffic.
        float w[D_CHUNK];
#pragma unroll
        for (int dd = 0; dd < D_CHUNK; dd++)
            w[dd] = W1[(size_t)(d0 + dd) * H_DIM + j];

        if (tid == 0) {
            while (atomicAdd(&g_c1, 0u) < N_BLOCKS) { }
            __threadfence();               // acquire
        }
        __syncthreads();

        // Means for this d-chunk into smem.
        for (int i = tid; i < B_DIM * D_CHUNK; i += 256) {
            int b = i / D_CHUNK, dd = i % D_CHUNK;
            s[b][dd] = g_colsum[b * E_DIM + d0 + dd] * (1.0f / (float)T_DIM);
        }
        __syncthreads();

        float a0 = 0.f, a1 = 0.f, a2 = 0.f, a3 = 0.f;
#pragma unroll
        for (int dd = 0; dd < D_CHUNK; dd++) {
            float ww = w[dd];
            a0 = fmaf(s[0][dd], ww, a0);
            a1 = fmaf(s[1][dd], ww, a1);
            a2 = fmaf(s[2][dd], ww, a2);
            a3 = fmaf(s[3][dd], ww, a3);
        }
        g_hpart[bid][0][j] = a0;
        g_hpart[bid][1][j] = a1;
        g_hpart[bid][2][j] = a2;
        g_hpart[bid][3][j] = a3;

        __syncthreads();
        if (tid == 0) {
            __threadfence();
            atomicAdd(&g_c2, 1u);
        }
    }

    // ---------------- Phase 3: epilogue (block 0) ---------------------------
    if (bid == 0) {
        if (tid == 0) {
            while (atomicAdd(&g_c2, 0u) < N_TAIL) { }
            __threadfence();
        }
        __syncthreads();

        __shared__ float red[B_DIM][8];
        const int j    = tid;
        const int lane = j & 31, warp = j >> 5;

        float w2 = W2[j];
        float bb = b1[j];
        float v[B_DIM];
#pragma unroll
        for (int b = 0; b < B_DIM; b++) {
            float h = bb;
#pragma unroll
            for (int p = 0; p < N_TAIL; p++) h += g_hpart[p][b][j];
            v[b] = fmaxf(h, 0.0f) * w2;
        }
#pragma unroll
        for (int off = 16; off > 0; off >>= 1)
#pragma unroll
            for (int b = 0; b < B_DIM; b++)
                v[b] += __shfl_down_sync(0xffffffffu, v[b], off);
        if (lane == 0)
#pragma unroll
            for (int b = 0; b < B_DIM; b++) red[b][warp] = v[b];
        __syncthreads();

        if (j < B_DIM && j < out_size) {
            float sm = 0.f;
#pragma unroll
            for (int w8 = 0; w8 < 8; w8++) sm += red[j][w8];
            out[j] = sm + b2[0];
        }
        // best_action_idx slot: argmax over 32 bit-identical entropies == 0
        // always (int 0 == float 0.0 bit pattern). Zero-fill the rest.
        for (int i = B_DIM + tid; i < out_size; i += 256)
            out[i] = 0.0f;

        // Reset scratch for the next replay (everyone else is done reading).
        __syncthreads();
        for (int i = tid; i < B_DIM * E_DIM; i += 256) g_colsum[i] = 0.0f;
        if (tid == 0) { g_c1 = 0u; g_c2 = 0u; }
    }
}

extern "C" void kernel_launch(void* const* d_in, const int* in_sizes, int n_in,
                              void* d_out, int out_size) {
    const float* x  = (const float*)d_in[0];
    const float* W1 = (const float*)d_in[1];
    const float* b1 = (const float*)d_in[2];
    const float* W2 = (const float*)d_in[3];
    const float* b2 = (const float*)d_in[4];
    float* out = (float*)d_out;

    curiosity_fused<<<N_BLOCKS, 256>>>(x, W1, b1, W2, b2, out, out_size);
}